// round 7
// baseline (speedup 1.0000x reference)
#include <cuda_runtime.h>
#include <cstdint>

// ---------------- problem constants ----------------
#define IN_F   4096
#define OUT_F  4096
#define M_TOT  8192          // 4 * 2048 tokens

// GEMM tiling (int8 path)
#define BM 128
#define BN 128
#define BK 128
#define KT (IN_F / BK)       // 32
#define THREADS 256
#define STAGES 4

// ---------------- device scratch (static, no runtime alloc) ----------------
__device__ int8_t g_Ah[(size_t)M_TOT * IN_F];    // 32 MB: x hi-level int8
__device__ int8_t g_Al[(size_t)M_TOT * IN_F];    // 32 MB: x lo-level int8
__device__ int8_t g_Wq[(size_t)OUT_F * IN_F];    // 16 MB: int4 weights as int8 (exact)
__device__ float  g_sx[M_TOT];                   // per-row x scale
__device__ float  g_xa[M_TOT * 16];              // x @ lora_A^T
__device__ float  g_LB[(size_t)M_TOT * OUT_F];   // 128 MB: bias + 2*(xa @ lora_B^T)

// ---------------- helpers ----------------
__device__ __forceinline__ uint32_t smem_u32(const void* p) {
    uint32_t a;
    asm("{ .reg .u64 t; cvta.to.shared.u64 t, %1; cvt.u32.u64 %0, t; }" : "=r"(a) : "l"(p));
    return a;
}
__device__ __forceinline__ void cp16(uint32_t s, const void* g) {
    asm volatile("{ .reg .u64 ga; cvta.to.global.u64 ga, %1; cp.async.cg.shared.global [%0], [ga], 16; }"
                 :: "r"(s), "l"(g));
}
#define CP_COMMIT() asm volatile("cp.async.commit_group;" ::: "memory")
#define CP_WAIT(n)  asm volatile("cp.async.wait_group %0;" :: "n"(n) : "memory")

__device__ __forceinline__ void ldsm4(uint32_t* r, uint32_t a) {
    asm volatile("ldmatrix.sync.aligned.m8n8.x4.shared.b16 {%0,%1,%2,%3}, [%4];"
                 : "=r"(r[0]), "=r"(r[1]), "=r"(r[2]), "=r"(r[3]) : "r"(a));
}
__device__ __forceinline__ void imma(int* c, const uint32_t* a, const uint32_t* b) {
    asm volatile("mma.sync.aligned.m16n8k32.row.col.s32.s8.s8.s32 "
                 "{%0,%1,%2,%3}, {%4,%5,%6,%7}, {%8,%9}, {%0,%1,%2,%3};"
                 : "+r"(c[0]), "+r"(c[1]), "+r"(c[2]), "+r"(c[3])
                 : "r"(a[0]), "r"(a[1]), "r"(a[2]), "r"(a[3]), "r"(b[0]), "r"(b[1]));
}

// ---------------- prologue 1: quantize x (two-level int8) ----------------
// one block per row; x kept in registers (16 f32/thread)
__global__ void __launch_bounds__(256) quant_x(const float* __restrict__ x)
{
    __shared__ float red[8];
    const int r = blockIdx.x, tid = threadIdx.x;
    const float4* xr = (const float4*)(x + (size_t)r * IN_F);
    float4 v[4];
    #pragma unroll
    for (int j = 0; j < 4; j++) v[j] = xr[tid + 256 * j];

    float m = 0.f;
    #pragma unroll
    for (int j = 0; j < 4; j++)
        m = fmaxf(m, fmaxf(fmaxf(fabsf(v[j].x), fabsf(v[j].y)),
                           fmaxf(fabsf(v[j].z), fabsf(v[j].w))));
    #pragma unroll
    for (int o = 16; o; o >>= 1) m = fmaxf(m, __shfl_xor_sync(~0u, m, o));
    if ((tid & 31) == 0) red[tid >> 5] = m;
    __syncthreads();
    m = red[0];
    #pragma unroll
    for (int j = 1; j < 8; j++) m = fmaxf(m, red[j]);
    m = fmaxf(m, 1e-20f);
    const float inv = 127.0f / m;
    if (tid == 0) g_sx[r] = m * (1.0f / 127.0f);

    char4* ah = (char4*)(g_Ah + (size_t)r * IN_F);
    char4* al = (char4*)(g_Al + (size_t)r * IN_F);
    #pragma unroll
    for (int j = 0; j < 4; j++) {
        float fx[4] = {v[j].x, v[j].y, v[j].z, v[j].w};
        int h[4], l[4];
        #pragma unroll
        for (int e = 0; e < 4; e++) {
            float s = fx[e] * inv;
            h[e] = __float2int_rn(s);
            l[e] = __float2int_rn((s - (float)h[e]) * 128.0f);
        }
        ah[tid + 256 * j] = make_char4((char)h[0], (char)h[1], (char)h[2], (char)h[3]);
        al[tid + 256 * j] = make_char4((char)l[0], (char)l[1], (char)l[2], (char)l[3]);
    }
}

// ---------------- prologue 2: int32 -> int8 weight cast (exact) ----------------
__global__ void __launch_bounds__(256) conv_w(const int* __restrict__ qw)
{
    size_t i = (size_t)blockIdx.x * 256 + threadIdx.x;
    int4 q = ((const int4*)qw)[i];
    ((char4*)g_Wq)[i] = make_char4((char)q.x, (char)q.y, (char)q.z, (char)q.w);
}

// ---------------- prologue 3: xa = x @ lora_A^T ----------------
__global__ void __launch_bounds__(256) zero_xa()
{
    g_xa[blockIdx.x * 256 + threadIdx.x] = 0.f;
}

// grid 8192: 1024 m-groups (8 rows, one per warp) x 8 k-blocks of 512
__global__ void __launch_bounds__(256) xa_gemm(const float* __restrict__ x, const float* __restrict__ lA)
{
    __shared__ float sAr[16][512];
    const int tid = threadIdx.x, wid = tid >> 5, lane = tid & 31;
    const int mb = blockIdx.x >> 3, kb = blockIdx.x & 7;
    const int k0 = kb * 512;
    #pragma unroll
    for (int j = 0; j < 32; j++) {
        int idx = tid + 256 * j;
        sAr[idx >> 9][idx & 511] = lA[(idx >> 9) * IN_F + k0 + (idx & 511)];
    }
    __syncthreads();

    const int m = mb * 8 + wid;
    const float* xp = x + (size_t)m * IN_F + k0;
    float acc[16];
    #pragma unroll
    for (int r = 0; r < 16; r++) acc[r] = 0.f;
    #pragma unroll 4
    for (int j = 0; j < 16; j++) {
        const int k = lane + 32 * j;
        const float xv = __ldg(xp + k);
        #pragma unroll
        for (int r = 0; r < 16; r++) acc[r] = fmaf(xv, sAr[r][k], acc[r]);
    }
    #pragma unroll
    for (int r = 0; r < 16; r++) {
        #pragma unroll
        for (int o = 16; o; o >>= 1) acc[r] += __shfl_xor_sync(~0u, acc[r], o);
    }
    if (lane == 0) {
        #pragma unroll
        for (int r = 0; r < 16; r++) atomicAdd(&g_xa[m * 16 + r], acc[r]);
    }
}

// ---------------- prologue 4: LB = bias + 2 * xa @ lora_B^T ----------------
__global__ void __launch_bounds__(256) lora_bias(const float* __restrict__ bias, const float* __restrict__ lB)
{
    __shared__ float sxa[128][17];
    __shared__ float sb[128][17];
    __shared__ float sbias[128];
    const int tid = threadIdx.x;
    const int m0 = (int)(blockIdx.x >> 5) * 128, o0 = (int)(blockIdx.x & 31) * 128;
    #pragma unroll
    for (int j = 0; j < 8; j++) {
        int idx = tid + 256 * j;
        sxa[idx >> 4][idx & 15] = g_xa[(m0 + (idx >> 4)) * 16 + (idx & 15)];
        sb [idx >> 4][idx & 15] = lB[(o0 + (idx >> 4)) * 16 + (idx & 15)];
    }
    if (tid < 128) sbias[tid] = bias[o0 + tid];
    __syncthreads();

    const int rb = (tid & 15) * 8, cb = (tid >> 4) * 8;
    float acc[8][8];
    #pragma unroll
    for (int a = 0; a < 8; a++)
        #pragma unroll
        for (int b = 0; b < 8; b++) acc[a][b] = 0.f;
    #pragma unroll
    for (int r = 0; r < 16; r++) {
        float xv[8], bv[8];
        #pragma unroll
        for (int j = 0; j < 8; j++) { xv[j] = sxa[rb + j][r]; bv[j] = sb[cb + j][r]; }
        #pragma unroll
        for (int a = 0; a < 8; a++)
            #pragma unroll
            for (int b = 0; b < 8; b++) acc[a][b] = fmaf(xv[a], bv[b], acc[a][b]);
    }
    #pragma unroll
    for (int a = 0; a < 8; a++) {
        float* op = g_LB + (size_t)(m0 + rb + a) * OUT_F + o0 + cb;
        #pragma unroll
        for (int b = 0; b < 8; b += 4) {
            float4 v;
            v.x = fmaf(2.f, acc[a][b + 0], sbias[cb + b + 0]);
            v.y = fmaf(2.f, acc[a][b + 1], sbias[cb + b + 1]);
            v.z = fmaf(2.f, acc[a][b + 2], sbias[cb + b + 2]);
            v.w = fmaf(2.f, acc[a][b + 3], sbias[cb + b + 3]);
            *(float4*)(op + b) = v;
        }
    }
}

// ---------------- main: int8 IMMA GEMM, 128x128 CTA tile, K-tile 128 ----------------
constexpr int AH_OFF = 0;
constexpr int AL_OFF = 16384;
constexpr int B_OFF  = 32768;
constexpr int STAGE_BYTES = 49152;
constexpr int SMEM_TOTAL  = STAGES * STAGE_BYTES;   // 196608

__device__ __forceinline__ void load_stage(uint32_t sb, int stage, int kt, int m0, int n0, int tid)
{
    const uint32_t st = sb + stage * STAGE_BYTES;
    const int kb = kt * BK;
    #pragma unroll
    for (int q = 0; q < 4; q++) {
        int ch = tid + 256 * q;          // 0..1023
        int row = ch >> 3, c = ch & 7;
        uint32_t so = (uint32_t)(row * 128 + ((c ^ (row & 7)) << 4));
        cp16(st + AH_OFF + so, g_Ah + (size_t)(m0 + row) * IN_F + kb + c * 16);
        cp16(st + AL_OFF + so, g_Al + (size_t)(m0 + row) * IN_F + kb + c * 16);
        cp16(st + B_OFF  + so, g_Wq + (size_t)(n0 + row) * IN_F + kb + c * 16);
    }
}

__global__ void __launch_bounds__(THREADS, 1)
gemm_i8(const float* __restrict__ qs, float* __restrict__ out)
{
    extern __shared__ __align__(1024) char smem[];
    const uint32_t sb = smem_u32(smem);
    const int tid = threadIdx.x, wid = tid >> 5, lane = tid & 31;
    const int m0 = (int)(blockIdx.x >> 5) * BM;   // n-fast: Wq stays L2-resident
    const int n0 = (int)(blockIdx.x & 31) * BN;
    const int wm = wid & 3, wn = wid >> 2;        // 4 m-groups x 2 n-groups, warp tile 32x64
    const int lane7 = lane & 7;

    // ldmatrix b8-as-b16 addressing (row&7 == lane7 for all tiles)
    const uint32_t aRow = (uint32_t)((wm * 32 + ((lane >> 3) & 1) * 8 + lane7) * 128);
    const uint32_t aSel = (uint32_t)((lane >> 4) & 1);
    const uint32_t bRow = (uint32_t)((wn * 64 + ((lane >> 4) & 1) * 8 + lane7) * 128);
    const uint32_t bSel = (uint32_t)((lane >> 3) & 1);

    int acch[2][8][4], accl[2][8][4];
    #pragma unroll
    for (int a = 0; a < 2; a++)
        #pragma unroll
        for (int b = 0; b < 8; b++)
            #pragma unroll
            for (int c = 0; c < 4; c++) { acch[a][b][c] = 0; accl[a][b][c] = 0; }

    #pragma unroll
    for (int s = 0; s < STAGES - 1; s++) {
        load_stage(sb, s, s, m0, n0, tid);
        CP_COMMIT();
    }

    #pragma unroll 1
    for (int kt = 0; kt < KT; kt++) {
        CP_WAIT(STAGES - 2);
        __syncthreads();
        if (kt + STAGES - 1 < KT)
            load_stage(sb, (kt + STAGES - 1) & (STAGES - 1), kt + STAGES - 1, m0, n0, tid);
        CP_COMMIT();

        const uint32_t st = sb + (kt & (STAGES - 1)) * STAGE_BYTES;
        #pragma unroll
        for (int ks = 0; ks < 4; ks++) {
            uint32_t bf[4][4];
            const uint32_t bc = ((((uint32_t)(ks << 1) | bSel) ^ lane7) << 4);
            #pragma unroll
            for (int i = 0; i < 4; i++)
                ldsm4(bf[i], st + B_OFF + bRow + i * 2048 + bc);
            const uint32_t ac = ((((uint32_t)(ks << 1) | aSel) ^ lane7) << 4);
            #pragma unroll
            for (int mf = 0; mf < 2; mf++) {
                uint32_t ah[4], al[4];
                ldsm4(ah, st + AH_OFF + aRow + mf * 2048 + ac);
                ldsm4(al, st + AL_OFF + aRow + mf * 2048 + ac);
                #pragma unroll
                for (int i = 0; i < 4; i++) {
                    imma(acch[mf][2 * i],     ah, &bf[i][0]);
                    imma(acch[mf][2 * i + 1], ah, &bf[i][2]);
                    imma(accl[mf][2 * i],     al, &bf[i][0]);
                    imma(accl[mf][2 * i + 1], al, &bf[i][2]);
                }
            }
        }
    }

    // epilogue: out = sx[m]*qs[o]*(hi + lo/128) + LB[m][o]  (ints exact in f32)
    #pragma unroll
    for (int mf = 0; mf < 2; mf++) {
        const int mr = m0 + wm * 32 + mf * 16 + (lane >> 2);
        const float sx0 = __ldg(&g_sx[mr]), sx1 = __ldg(&g_sx[mr + 8]);
        float* o0p = out + (size_t)mr * OUT_F;
        float* o1p = out + (size_t)(mr + 8) * OUT_F;
        const float* l0p = g_LB + (size_t)mr * OUT_F;
        const float* l1p = g_LB + (size_t)(mr + 8) * OUT_F;
        #pragma unroll
        for (int nf = 0; nf < 8; nf++) {
            const int c = n0 + wn * 64 + nf * 8 + (lane & 3) * 2;
            const float s0 = __ldg(qs + c), s1 = __ldg(qs + c + 1);
            const float2 lb0 = *(const float2*)(l0p + c);
            const float2 lb1 = *(const float2*)(l1p + c);
            const int* h = acch[mf][nf];
            const int* l = accl[mf][nf];
            float2 r0, r1;
            r0.x = fmaf(fmaf((float)l[0], 0.0078125f, (float)h[0]), sx0 * s0, lb0.x);
            r0.y = fmaf(fmaf((float)l[1], 0.0078125f, (float)h[1]), sx0 * s1, lb0.y);
            r1.x = fmaf(fmaf((float)l[2], 0.0078125f, (float)h[2]), sx1 * s0, lb1.x);
            r1.y = fmaf(fmaf((float)l[3], 0.0078125f, (float)h[3]), sx1 * s1, lb1.y);
            *(float2*)(o0p + c) = r0;
            *(float2*)(o1p + c) = r1;
        }
    }
}

// ---------------- launch ----------------
extern "C" void kernel_launch(void* const* d_in, const int* in_sizes, int n_in,
                              void* d_out, int out_size)
{
    const float* x    = (const float*)d_in[0];
    const int*   qw   = (const int*)  d_in[1];
    const float* qs   = (const float*)d_in[2];
    const float* bias = (const float*)d_in[3];
    const float* lA   = (const float*)d_in[4];
    const float* lB   = (const float*)d_in[5];
    float* out = (float*)d_out;

    cudaFuncSetAttribute(gemm_i8, cudaFuncAttributeMaxDynamicSharedMemorySize, SMEM_TOTAL);

    quant_x<<<M_TOT, 256>>>(x);
    conv_w<<<(int)((size_t)OUT_F * IN_F / 4 / 256), 256>>>(qw);
    zero_xa<<<M_TOT * 16 / 256, 256>>>();
    xa_gemm<<<8192, 256>>>(x, lA);
    lora_bias<<<(M_TOT / 128) * (OUT_F / 128), 256>>>(bias, lB);
    gemm_i8<<<(M_TOT / BM) * (OUT_F / BN), THREADS, SMEM_TOTAL>>>(qs, out);
}

// round 8
// speedup vs baseline: 5.4913x; 5.4913x over previous
#include <cuda_runtime.h>
#include <cuda_fp16.h>
#include <cstdint>

// ---------------- problem constants ----------------
#define IN_F   4096
#define OUT_F  4096
#define M_TOT  8192          // 4 * 2048 tokens

// GEMM tiling (fp16 path)
#define BM 256
#define BN 128
#define BK 64                // 64 fp16 = 128 bytes per row
#define KTILES (IN_F / BK)   // 64
#define THREADS 512
#define STAGES 4

// device scratch (static __device__ arrays; no runtime alloc)
__device__ __half g_W[(size_t)OUT_F * IN_F];   // 32 MB: W_eff = q*s + 2*(B@A), fp16
__device__ __half g_X[(size_t)M_TOT * IN_F];   // 64 MB: x, fp16

// ---------------- helpers ----------------
__device__ __forceinline__ uint32_t smem_u32(const void* p) {
    uint32_t a;
    asm("{ .reg .u64 t; cvta.to.shared.u64 t, %1; cvt.u32.u64 %0, t; }" : "=r"(a) : "l"(p));
    return a;
}
__device__ __forceinline__ void cp16(uint32_t s, const void* g) {
    asm volatile("{ .reg .u64 ga; cvta.to.global.u64 ga, %1; cp.async.cg.shared.global [%0], [ga], 16; }"
                 :: "r"(s), "l"(g));
}
#define CP_COMMIT() asm volatile("cp.async.commit_group;" ::: "memory")
#define CP_WAIT(n)  asm volatile("cp.async.wait_group %0;" :: "n"(n) : "memory")

__device__ __forceinline__ void ldsm4(uint32_t* r, uint32_t a) {
    asm volatile("ldmatrix.sync.aligned.m8n8.x4.shared.b16 {%0,%1,%2,%3}, [%4];"
                 : "=r"(r[0]), "=r"(r[1]), "=r"(r[2]), "=r"(r[3]) : "r"(a));
}
__device__ __forceinline__ void mma16816(float* c, const uint32_t* a, const uint32_t* b) {
    asm volatile("mma.sync.aligned.m16n8k16.row.col.f32.f16.f16.f32 "
                 "{%0,%1,%2,%3}, {%4,%5,%6,%7}, {%8,%9}, {%0,%1,%2,%3};"
                 : "+f"(c[0]), "+f"(c[1]), "+f"(c[2]), "+f"(c[3])
                 : "r"(a[0]), "r"(a[1]), "r"(a[2]), "r"(a[3]), "r"(b[0]), "r"(b[1]));
}

// ---------------- stage 1a: W_eff = q*s + 2*(B@A) -> fp16 ----------------
// grid: (OUT_F/16) * (IN_F/512) = 2048 blocks, 256 threads
__global__ void __launch_bounds__(256)
build_weff(const int* __restrict__ qw, const float* __restrict__ qs,
           const float* __restrict__ lA, const float* __restrict__ lB)
{
    __shared__ float sA[16 * 512];
    __shared__ float sB[16 * 16];
    __shared__ float sS[16];
    const int tid = threadIdx.x;
    const int o0 = (blockIdx.x >> 3) * 16;
    const int i0 = (blockIdx.x & 7) * 512;

    #pragma unroll
    for (int j = 0; j < 32; j++) {
        int idx = tid + 256 * j;
        sA[idx] = lA[(idx >> 9) * IN_F + i0 + (idx & 511)];
    }
    sB[tid & 255] = lB[(o0 + ((tid & 255) >> 4)) * 16 + (tid & 15)];
    if (tid < 16) sS[tid] = qs[o0 + tid];
    __syncthreads();

    #pragma unroll 4
    for (int j = 0; j < 32; j++) {
        int idx = tid + 256 * j;
        int ol = idx >> 9, ii = idx & 511;
        float acc = 0.f;
        #pragma unroll
        for (int r = 0; r < 16; r++) acc = fmaf(sB[ol * 16 + r], sA[r * 512 + ii], acc);
        size_t gidx = (size_t)(o0 + ol) * IN_F + i0 + ii;
        float w = fmaf((float)qw[gidx], sS[ol], 2.0f * acc);
        g_W[gidx] = __float2half_rn(w);
    }
}

// ---------------- stage 1b: x -> fp16 ----------------
// 8 floats per thread -> one 16B half store
__global__ void __launch_bounds__(256)
round_x(const float* __restrict__ x)
{
    size_t i = ((size_t)blockIdx.x * 256 + threadIdx.x) * 8;
    float4 a = *(const float4*)(x + i);
    float4 b = *(const float4*)(x + i + 4);
    __half2 h[4];
    h[0] = __floats2half2_rn(a.x, a.y);
    h[1] = __floats2half2_rn(a.z, a.w);
    h[2] = __floats2half2_rn(b.x, b.y);
    h[3] = __floats2half2_rn(b.z, b.w);
    *(uint4*)(g_X + i) = *(uint4*)h;
}

// ---------------- stage 2: fp16 mma.sync GEMM, 256x128 CTA tile, BK=64 ----------------
constexpr int A_BYTES     = BM * BK * 2;           // 32768  (256 rows x 128B)
constexpr int B_BYTES     = BN * BK * 2;           // 16384  (128 rows x 128B)
constexpr int STAGE_BYTES = A_BYTES + B_BYTES;     // 49152
constexpr int SMEM_TOTAL  = STAGES * STAGE_BYTES;  // 196608

__device__ __forceinline__ void load_stage(uint32_t sb, int stage, int kt,
                                           int m0, int n0, int tid)
{
    const __half* gx = g_X + (size_t)m0 * IN_F + kt * BK;
    const __half* gw = g_W + (size_t)n0 * IN_F + kt * BK;
    const uint32_t sa = sb + stage * STAGE_BYTES;
    const uint32_t sbb = sa + A_BYTES;
    // A: 256 rows x 8 chunks(16B) = 2048 chunks, 4 per thread
    #pragma unroll
    for (int q = 0; q < 4; q++) {
        int chunk = tid + THREADS * q;
        int row = chunk >> 3, c = chunk & 7;
        uint32_t so = sa + row * 128 + ((c * 16) ^ ((row & 7) * 16));
        cp16(so, gx + (size_t)row * IN_F + c * 8);
    }
    // B: 128 rows x 8 chunks = 1024 chunks, 2 per thread
    #pragma unroll
    for (int q = 0; q < 2; q++) {
        int chunk = tid + THREADS * q;
        int row = chunk >> 3, c = chunk & 7;
        uint32_t so = sbb + row * 128 + ((c * 16) ^ ((row & 7) * 16));
        cp16(so, gw + (size_t)row * IN_F + c * 8);
    }
}

__global__ void __launch_bounds__(THREADS, 1)
gemm_mma(const float* __restrict__ bias, float* __restrict__ out)
{
    extern __shared__ __align__(1024) char smem[];
    const uint32_t sb = smem_u32(smem);
    const int tid = threadIdx.x, wid = tid >> 5, lane = tid & 31;
    const int m0 = (int)(blockIdx.x >> 5) * BM;   // n-fast ordering: W stays L2-resident
    const int n0 = (int)(blockIdx.x & 31) * BN;

    const int warp_m = (wid & 3) * 64;   // 4 warps along M
    const int warp_n = (wid >> 2) * 32;  // 4 warps along N

    // ldmatrix lane addressing (16B chunks; identical formulas to the proven tf32 kernel)
    const int t = lane >> 3, r8 = lane & 7;
    // A frag (m16k16): r0: m+0..7,k0..7 | r1: m+8..15,k0..7 | r2: m+0..7,k8..15 | r3: m+8..15,k8..15
    const uint32_t aRow128 = (uint32_t)(warp_m + r8 + (t & 1) * 8) * 128;
    const uint32_t aC = (uint32_t)(((t >> 1) * 16) ^ (r8 * 16));
    // B frag (n8k16, n-major smem): r0: n0..7,k0..7 | r1: n0..7,k8..15 | r2: n8..15,k0..7 | r3: n8..15,k8..15
    const uint32_t bRow128 = (uint32_t)(warp_n + (t >> 1) * 8 + r8) * 128;
    const uint32_t bC = (uint32_t)(((t & 1) * 16) ^ (r8 * 16));

    float acc[4][4][4];
    #pragma unroll
    for (int a = 0; a < 4; a++)
        #pragma unroll
        for (int b = 0; b < 4; b++)
            #pragma unroll
            for (int c = 0; c < 4; c++) acc[a][b][c] = 0.f;

    #pragma unroll
    for (int s = 0; s < STAGES - 1; s++) {
        load_stage(sb, s, s, m0, n0, tid);
        CP_COMMIT();
    }

    #pragma unroll 1
    for (int kt = 0; kt < KTILES; kt++) {
        CP_WAIT(STAGES - 2);
        __syncthreads();

        // issue next stage first so cp.async overlaps the mma work
        if (kt + STAGES - 1 < KTILES)
            load_stage(sb, (kt + STAGES - 1) & (STAGES - 1), kt + STAGES - 1, m0, n0, tid);
        CP_COMMIT();

        const uint32_t sa = sb + (kt & (STAGES - 1)) * STAGE_BYTES;
        const uint32_t sB = sa + A_BYTES;

        #pragma unroll
        for (int ks = 0; ks < 4; ks++) {          // 4 x k16 per BK=64 tile
            const uint32_t koff = (uint32_t)(ks << 5);   // 32 bytes = 16 fp16
            uint32_t bf[2][4];
            ldsm4(bf[0], sB + bRow128 +        (koff ^ bC));   // n 0..15
            ldsm4(bf[1], sB + bRow128 + 2048 + (koff ^ bC));   // n 16..31
            #pragma unroll
            for (int mf = 0; mf < 4; mf++) {
                uint32_t af[4];
                ldsm4(af, sa + aRow128 + mf * 2048 + (koff ^ aC));
                #pragma unroll
                for (int i = 0; i < 2; i++) {
                    mma16816(acc[mf][2 * i],     af, &bf[i][0]);
                    mma16816(acc[mf][2 * i + 1], af, &bf[i][2]);
                }
            }
        }
    }

    // epilogue: c0/c1 -> (row, col..col+1), c2/c3 -> (row+8, col..col+1)
    const int row0 = m0 + warp_m + (lane >> 2);
    const int col0 = n0 + warp_n + (lane & 3) * 2;
    #pragma unroll
    for (int mf = 0; mf < 4; mf++) {
        #pragma unroll
        for (int nf = 0; nf < 4; nf++) {
            const int c = col0 + nf * 8;
            const float b0 = __ldg(bias + c), b1 = __ldg(bias + c + 1);
            const int rr = row0 + mf * 16;
            float2 v0 = { acc[mf][nf][0] + b0, acc[mf][nf][1] + b1 };
            float2 v1 = { acc[mf][nf][2] + b0, acc[mf][nf][3] + b1 };
            *(float2*)(out + (size_t)rr * OUT_F + c)       = v0;
            *(float2*)(out + (size_t)(rr + 8) * OUT_F + c) = v1;
        }
    }
}

// ---------------- launch ----------------
extern "C" void kernel_launch(void* const* d_in, const int* in_sizes, int n_in,
                              void* d_out, int out_size)
{
    const float* x    = (const float*)d_in[0];
    const int*   qw   = (const int*)  d_in[1];
    const float* qs   = (const float*)d_in[2];
    const float* bias = (const float*)d_in[3];
    const float* lA   = (const float*)d_in[4];
    const float* lB   = (const float*)d_in[5];
    float* out = (float*)d_out;

    cudaFuncSetAttribute(gemm_mma, cudaFuncAttributeMaxDynamicSharedMemorySize, SMEM_TOTAL);

    build_weff<<<(OUT_F / 16) * (IN_F / 512), 256>>>(qw, qs, lA, lB);
    round_x<<<(int)((size_t)M_TOT * IN_F / 8 / 256), 256>>>(x);
    gemm_mma<<<(M_TOT / BM) * (OUT_F / BN), THREADS, SMEM_TOTAL>>>(bias, out);
}

// round 9
// speedup vs baseline: 5.4976x; 1.0011x over previous
#include <cuda_runtime.h>
#include <cuda_fp16.h>
#include <cstdint>

// ---------------- problem constants ----------------
#define IN_F   4096
#define OUT_F  4096
#define M_TOT  8192          // 4 * 2048 tokens

// GEMM tiling (fp16 path)
#define BM 256
#define BN 128
#define BK 64                // 64 fp16 = 128 bytes per row
#define KTILES (IN_F / BK)   // 64
#define THREADS 256          // 8 warps, warp tile 64x64
#define STAGES 4

// device scratch (static __device__ arrays; no runtime alloc)
__device__ __half g_W[(size_t)OUT_F * IN_F];   // 32 MB: W_eff = q*s + 2*(B@A), fp16
__device__ __half g_X[(size_t)M_TOT * IN_F];   // 64 MB: x, fp16

// ---------------- helpers ----------------
__device__ __forceinline__ uint32_t smem_u32(const void* p) {
    uint32_t a;
    asm("{ .reg .u64 t; cvta.to.shared.u64 t, %1; cvt.u32.u64 %0, t; }" : "=r"(a) : "l"(p));
    return a;
}
__device__ __forceinline__ void cp16(uint32_t s, const void* g) {
    asm volatile("{ .reg .u64 ga; cvta.to.global.u64 ga, %1; cp.async.cg.shared.global [%0], [ga], 16; }"
                 :: "r"(s), "l"(g));
}
#define CP_COMMIT() asm volatile("cp.async.commit_group;" ::: "memory")
#define CP_WAIT(n)  asm volatile("cp.async.wait_group %0;" :: "n"(n) : "memory")

__device__ __forceinline__ void ldsm4(uint32_t* r, uint32_t a) {
    asm volatile("ldmatrix.sync.aligned.m8n8.x4.shared.b16 {%0,%1,%2,%3}, [%4];"
                 : "=r"(r[0]), "=r"(r[1]), "=r"(r[2]), "=r"(r[3]) : "r"(a));
}
__device__ __forceinline__ void mma16816(float* c, const uint32_t* a, const uint32_t* b) {
    asm volatile("mma.sync.aligned.m16n8k16.row.col.f32.f16.f16.f32 "
                 "{%0,%1,%2,%3}, {%4,%5,%6,%7}, {%8,%9}, {%0,%1,%2,%3};"
                 : "+f"(c[0]), "+f"(c[1]), "+f"(c[2]), "+f"(c[3])
                 : "r"(a[0]), "r"(a[1]), "r"(a[2]), "r"(a[3]), "r"(b[0]), "r"(b[1]));
}

// ---------------- stage 1a: W_eff = q*s + 2*(B@A) -> fp16 (register-blocked) ----------------
// tile: 16 o x 512 i per block; thread owns 2 o x 16 i (4 float4-columns at lane*4 + j*128)
// grid: (OUT_F/16) * (IN_F/512) = 2048 blocks, 256 threads
__global__ void __launch_bounds__(256)
build_weff(const int* __restrict__ qw, const float* __restrict__ qs,
           const float* __restrict__ lA, const float* __restrict__ lB)
{
    __shared__ float4 sA[16 * 128];     // 16 rows x 512 floats
    const int tid = threadIdx.x;
    const int o0 = (blockIdx.x >> 3) * 16;
    const int i0 = (blockIdx.x & 7) * 512;

    // cooperative load of the lora_A panel (float4, coalesced)
    #pragma unroll
    for (int j = 0; j < 8; j++) {
        int idx = tid + 256 * j;                 // 0..2047
        int row = idx >> 7, c4 = idx & 127;
        sA[idx] = *(const float4*)(lA + (size_t)row * IN_F + i0 + c4 * 4);
    }

    const int op = tid >> 5;                     // 0..7 -> o pair
    const int ic = tid & 31;                     // lane -> i base (ic*4)
    const int oa = o0 + op * 2, ob = oa + 1;

    // lora_B rows for the two o's in registers (L1-cached redundant loads)
    float Ba[16], Bb[16];
    #pragma unroll
    for (int r = 0; r < 4; r++) {
        float4 va = *(const float4*)(lB + (size_t)oa * 16 + r * 4);
        float4 vb = *(const float4*)(lB + (size_t)ob * 16 + r * 4);
        Ba[4*r] = va.x; Ba[4*r+1] = va.y; Ba[4*r+2] = va.z; Ba[4*r+3] = va.w;
        Bb[4*r] = vb.x; Bb[4*r+1] = vb.y; Bb[4*r+2] = vb.z; Bb[4*r+3] = vb.w;
    }
    const float sa = __ldg(qs + oa), sb2 = __ldg(qs + ob);
    __syncthreads();

    float4 acc[2][4];
    #pragma unroll
    for (int j = 0; j < 4; j++) {
        acc[0][j] = make_float4(0.f, 0.f, 0.f, 0.f);
        acc[1][j] = make_float4(0.f, 0.f, 0.f, 0.f);
    }
    #pragma unroll
    for (int r = 0; r < 16; r++) {
        const float ba = Ba[r], bb = Bb[r];
        #pragma unroll
        for (int j = 0; j < 4; j++) {
            float4 a = sA[r * 128 + ic + j * 32];    // lane-stride 16B: conflict-free phases
            acc[0][j].x = fmaf(ba, a.x, acc[0][j].x); acc[0][j].y = fmaf(ba, a.y, acc[0][j].y);
            acc[0][j].z = fmaf(ba, a.z, acc[0][j].z); acc[0][j].w = fmaf(ba, a.w, acc[0][j].w);
            acc[1][j].x = fmaf(bb, a.x, acc[1][j].x); acc[1][j].y = fmaf(bb, a.y, acc[1][j].y);
            acc[1][j].z = fmaf(bb, a.z, acc[1][j].z); acc[1][j].w = fmaf(bb, a.w, acc[1][j].w);
        }
    }

    #pragma unroll
    for (int e = 0; e < 2; e++) {
        const int o = e ? ob : oa;
        const float s = e ? sb2 : sa;
        #pragma unroll
        for (int j = 0; j < 4; j++) {
            const size_t gi = (size_t)o * IN_F + i0 + ic * 4 + j * 128;
            int4 q = *(const int4*)(qw + gi);
            float4 a = e ? acc[1][j] : acc[0][j];
            __half2 h0 = __floats2half2_rn(fmaf((float)q.x, s, 2.f * a.x),
                                           fmaf((float)q.y, s, 2.f * a.y));
            __half2 h1 = __floats2half2_rn(fmaf((float)q.z, s, 2.f * a.z),
                                           fmaf((float)q.w, s, 2.f * a.w));
            *(uint2*)(g_W + gi) = make_uint2(*(uint32_t*)&h0, *(uint32_t*)&h1);
        }
    }
}

// ---------------- stage 1b: x -> fp16 ----------------
__global__ void __launch_bounds__(256)
round_x(const float* __restrict__ x)
{
    size_t i = ((size_t)blockIdx.x * 256 + threadIdx.x) * 8;
    float4 a = *(const float4*)(x + i);
    float4 b = *(const float4*)(x + i + 4);
    __half2 h[4];
    h[0] = __floats2half2_rn(a.x, a.y);
    h[1] = __floats2half2_rn(a.z, a.w);
    h[2] = __floats2half2_rn(b.x, b.y);
    h[3] = __floats2half2_rn(b.z, b.w);
    *(uint4*)(g_X + i) = *(uint4*)h;
}

// ---------------- stage 2: fp16 mma.sync GEMM, 256x128 CTA tile, warp tile 64x64 ----------------
constexpr int A_BYTES     = BM * BK * 2;           // 32768  (256 rows x 128B)
constexpr int B_BYTES     = BN * BK * 2;           // 16384  (128 rows x 128B)
constexpr int STAGE_BYTES = A_BYTES + B_BYTES;     // 49152
constexpr int SMEM_TOTAL  = STAGES * STAGE_BYTES;  // 196608

__device__ __forceinline__ void load_stage(uint32_t sb, int stage, int kt,
                                           int m0, int n0, int tid)
{
    const __half* gx = g_X + (size_t)m0 * IN_F + kt * BK;
    const __half* gw = g_W + (size_t)n0 * IN_F + kt * BK;
    const uint32_t sa = sb + stage * STAGE_BYTES;
    const uint32_t sbb = sa + A_BYTES;
    // A: 256 rows x 8 chunks(16B) = 2048 chunks, 8 per thread
    #pragma unroll
    for (int q = 0; q < 8; q++) {
        int chunk = tid + THREADS * q;
        int row = chunk >> 3, c = chunk & 7;
        uint32_t so = sa + row * 128 + ((c * 16) ^ ((row & 7) * 16));
        cp16(so, gx + (size_t)row * IN_F + c * 8);
    }
    // B: 128 rows x 8 chunks = 1024 chunks, 4 per thread
    #pragma unroll
    for (int q = 0; q < 4; q++) {
        int chunk = tid + THREADS * q;
        int row = chunk >> 3, c = chunk & 7;
        uint32_t so = sbb + row * 128 + ((c * 16) ^ ((row & 7) * 16));
        cp16(so, gw + (size_t)row * IN_F + c * 8);
    }
}

__global__ void __launch_bounds__(THREADS, 1)
gemm_mma(const float* __restrict__ bias, float* __restrict__ out)
{
    extern __shared__ __align__(1024) char smem[];
    const uint32_t sb = smem_u32(smem);
    const int tid = threadIdx.x, wid = tid >> 5, lane = tid & 31;
    const int m0 = (int)(blockIdx.x >> 5) * BM;   // n-fast ordering: W stays L2-resident
    const int n0 = (int)(blockIdx.x & 31) * BN;

    const int warp_m = (wid & 3) * 64;   // 4 warp-rows along M
    const int warp_n = (wid >> 2) * 64;  // 2 warp-cols along N

    // ldmatrix lane addressing (identical formulas to the proven fp16 kernel)
    const int t = lane >> 3, r8 = lane & 7;
    // A frag (m16k16): r0: m+0..7,k0..7 | r1: m+8..15,k0..7 | r2: +0..7,k8..15 | r3: +8..15,k8..15
    const uint32_t aRow128 = (uint32_t)(warp_m + r8 + (t & 1) * 8) * 128;
    const uint32_t aC = (uint32_t)(((t >> 1) * 16) ^ (r8 * 16));
    // B frag (n8k16, n-major smem): r0: n0..7,k0..7 | r1: n0..7,k8..15 | r2: n8..15,k0..7 | r3: n8..15,k8..15
    const uint32_t bRow128 = (uint32_t)(warp_n + (t >> 1) * 8 + r8) * 128;
    const uint32_t bC = (uint32_t)(((t & 1) * 16) ^ (r8 * 16));

    float acc[4][8][4];
    #pragma unroll
    for (int a = 0; a < 4; a++)
        #pragma unroll
        for (int b = 0; b < 8; b++)
            #pragma unroll
            for (int c = 0; c < 4; c++) acc[a][b][c] = 0.f;

    #pragma unroll
    for (int s = 0; s < STAGES - 1; s++) {
        load_stage(sb, s, s, m0, n0, tid);
        CP_COMMIT();
    }

    #pragma unroll 1
    for (int kt = 0; kt < KTILES; kt++) {
        CP_WAIT(STAGES - 2);
        __syncthreads();

        // issue next stage first so cp.async overlaps the mma work
        if (kt + STAGES - 1 < KTILES)
            load_stage(sb, (kt + STAGES - 1) & (STAGES - 1), kt + STAGES - 1, m0, n0, tid);
        CP_COMMIT();

        const uint32_t sa = sb + (kt & (STAGES - 1)) * STAGE_BYTES;
        const uint32_t sB = sa + A_BYTES;

        #pragma unroll
        for (int ks = 0; ks < 4; ks++) {          // 4 x k16 per BK=64 tile
            const uint32_t koff = (uint32_t)(ks << 5);   // 32 bytes = 16 fp16
            uint32_t bf[4][4];
            #pragma unroll
            for (int i = 0; i < 4; i++)           // n 0..63 of this warp
                ldsm4(bf[i], sB + bRow128 + i * 2048 + (koff ^ bC));
            #pragma unroll
            for (int mf = 0; mf < 4; mf++) {
                uint32_t af[4];
                ldsm4(af, sa + aRow128 + mf * 2048 + (koff ^ aC));
                #pragma unroll
                for (int i = 0; i < 4; i++) {
                    mma16816(acc[mf][2 * i],     af, &bf[i][0]);
                    mma16816(acc[mf][2 * i + 1], af, &bf[i][2]);
                }
            }
        }
    }

    // epilogue: c0/c1 -> (row, col..col+1), c2/c3 -> (row+8, col..col+1)
    const int row0 = m0 + warp_m + (lane >> 2);
    const int col0 = n0 + warp_n + (lane & 3) * 2;
    #pragma unroll
    for (int mf = 0; mf < 4; mf++) {
        #pragma unroll
        for (int nf = 0; nf < 8; nf++) {
            const int c = col0 + nf * 8;
            const float b0 = __ldg(bias + c), b1 = __ldg(bias + c + 1);
            const int rr = row0 + mf * 16;
            float2 v0 = { acc[mf][nf][0] + b0, acc[mf][nf][1] + b1 };
            float2 v1 = { acc[mf][nf][2] + b0, acc[mf][nf][3] + b1 };
            *(float2*)(out + (size_t)rr * OUT_F + c)       = v0;
            *(float2*)(out + (size_t)(rr + 8) * OUT_F + c) = v1;
        }
    }
}

// ---------------- launch ----------------
extern "C" void kernel_launch(void* const* d_in, const int* in_sizes, int n_in,
                              void* d_out, int out_size)
{
    const float* x    = (const float*)d_in[0];
    const int*   qw   = (const int*)  d_in[1];
    const float* qs   = (const float*)d_in[2];
    const float* bias = (const float*)d_in[3];
    const float* lA   = (const float*)d_in[4];
    const float* lB   = (const float*)d_in[5];
    float* out = (float*)d_out;

    cudaFuncSetAttribute(gemm_mma, cudaFuncAttributeMaxDynamicSharedMemorySize, SMEM_TOTAL);

    build_weff<<<(OUT_F / 16) * (IN_F / 512), 256>>>(qw, qs, lA, lB);
    round_x<<<(int)((size_t)M_TOT * IN_F / 8 / 256), 256>>>(x);
    gemm_mma<<<(M_TOT / BM) * (OUT_F / BN), THREADS, SMEM_TOTAL>>>(bias, out);
}